// round 15
// baseline (speedup 1.0000x reference)
#include <cuda_runtime.h>
#include <cstdint>

#define B     128
#define NIN   784
#define NEXC  400
#define T     500
#define NW_IN 25
#define NW_EX 13
#define JT    64
#define NJT   7
#define NCHUNK 42

typedef unsigned long long ull;

// -------- device scratch --------
__device__ float    g_D[(size_t)B * T * NEXC];
__device__ unsigned g_xbits[B * NW_IN * T];
__device__ unsigned g_sbits[B * NW_EX * T];
__device__ float    g_wie[(NEXC + 1) * NEXC];
__device__ float    g_colsum[NEXC];

// ---------------- K0a: masked/relu'd w_ie (+ zero pad row 400) --------------
__global__ void k_prep(const float* __restrict__ w)
{
    int idx = blockIdx.x * 256 + threadIdx.x;
    if (idx < (NEXC + 1) * NEXC) {
        float val = 0.f;
        if (idx < NEXC * NEXC) {
            int i = idx / NEXC, jj = idx - i * NEXC;
            float ww = w[idx];
            val = (i == jj) ? 0.f : fmaxf(ww, 0.f);
        }
        g_wie[idx] = val;
    }
}

// ---------------- K0b: column sums — 4-lane mod-4 + faddp tree --------------
// lane l sums rows i ≡ l (mod 4), ascending; result = (l0+l1)+(l2+l3).
__global__ void k_colsum()
{
    int j = blockIdx.x * 128 + threadIdx.x;
    if (j < NEXC) {
        float a0 = 0.f, a1 = 0.f, a2 = 0.f, a3 = 0.f;
        for (int i = 0; i < NEXC; i += 4) {
            a0 = __fadd_rn(a0, g_wie[(i + 0) * NEXC + j]);
            a1 = __fadd_rn(a1, g_wie[(i + 1) * NEXC + j]);
            a2 = __fadd_rn(a2, g_wie[(i + 2) * NEXC + j]);
            a3 = __fadd_rn(a3, g_wie[(i + 3) * NEXC + j]);
        }
        g_colsum[j] = __fadd_rn(__fadd_rn(a0, a1), __fadd_rn(a2, a3));
    }
}

// ---------------- K1: bit-pack input spikes ---------------------------------
__global__ void __launch_bounds__(512) k_bitpack(const float* __restrict__ x)
{
    int blk = blockIdx.x;
    int b = blk / NW_IN, iw = blk - b * NW_IN;
    int t = threadIdx.x;
    if (t >= T) return;
    int ibase = iw * 32;
    int nbits = min(32, NIN - ibase);
    const float* xp = x + ((size_t)b * NIN + ibase) * T + t;
    unsigned word = 0u;
    for (int r = 0; r < nbits; r++) {
        float v = xp[(size_t)r * T];
        word |= (v != 0.0f ? 1u : 0u) << r;
    }
    g_xbits[(b * NW_IN + iw) * T + t] = word;
}

// ---------------- K2: sparse drive, 4-lane mod-4 + faddp tree ---------------
// Ref hypothesis: NEON k-vectorized dot — lane l accumulates i ≡ l (mod 4)
// (zeros are exact no-ops -> skip inactive), final (l0+l1)+(l2+l3).
// Bit r of word iw has i = iw*32 + r, so lane = r & 3; sub-masks select lanes.
__global__ void __launch_bounds__(512) k_drive(const float* __restrict__ w_in)
{
    extern __shared__ float ws[];
    const int jt = blockIdx.x;
    const int chunk = blockIdx.y;
    const int j0 = jt * JT;

    for (int idx = threadIdx.x; idx < NIN * JT; idx += 512) {
        int i = idx >> 6, c = idx & 63;
        int j = j0 + c;
        ws[idx] = (j < NEXC) ? fmaxf(w_in[i * NEXC + j], 0.f) : 0.f;
    }
    __syncthreads();

    const int warp = threadIdx.x >> 5, lane = threadIdx.x & 31;
    const int per = (B * T + NCHUNK - 1) / NCHUNK;
    const int bt0 = chunk * per;
    const int btend = min(B * T, bt0 + per);

    for (int base = bt0 + warp * 2; base < btend; base += 16 * 2) {
        unsigned mw[2];
        ull pacc[2][4];
        #pragma unroll
        for (int c = 0; c < 2; c++) {
            int bt = base + c;
            unsigned m = 0u;
            if (bt < btend && lane < NW_IN) {
                int b = bt / T, t = bt - b * T;
                m = g_xbits[(b * NW_IN + lane) * T + t];
            }
            mw[c] = m;
            #pragma unroll
            for (int l2 = 0; l2 < 4; l2++) pacc[c][l2] = 0ull;
        }

        #pragma unroll
        for (int iw = 0; iw < NW_IN; iw++) {
            #pragma unroll
            for (int c = 0; c < 2; c++) {
                unsigned word = __shfl_sync(0xFFFFFFFFu, mw[c], iw);
                #pragma unroll
                for (int l2 = 0; l2 < 4; l2++) {
                    unsigned sw = word & (0x11111111u << l2);
                    while (sw) {
                        int r = __ffs(sw) - 1;
                        sw &= sw - 1;
                        ull wv = *reinterpret_cast<const ull*>(
                            &ws[(iw * 32 + r) * JT + 2 * lane]);
                        asm("add.rn.f32x2 %0, %0, %1;" : "+l"(pacc[c][l2]) : "l"(wv));
                    }
                }
            }
        }

        const int j = j0 + 2 * lane;
        if (j < NEXC) {
            #pragma unroll
            for (int c = 0; c < 2; c++) {
                int bt = base + c;
                if (bt < btend) {
                    ull t01 = 0ull, t23 = 0ull, res = 0ull;
                    asm("add.rn.f32x2 %0, %1, %2;" : "=l"(t01) : "l"(pacc[c][0]), "l"(pacc[c][1]));
                    asm("add.rn.f32x2 %0, %1, %2;" : "=l"(t23) : "l"(pacc[c][2]), "l"(pacc[c][3]));
                    asm("add.rn.f32x2 %0, %1, %2;" : "=l"(res) : "l"(t01), "l"(t23));
                    *reinterpret_cast<ull*>(&g_D[(size_t)bt * NEXC + j]) = res;
                }
            }
        }
    }
}

// ---------------- K3: recurrence; inh = 4-lane mod-4 + faddp tree -----------
// Active-row gather bucketed by i&3 (uniform branch per warp: all threads
// share the list). Pad index 400 (lane 0) has zero weight -> exact no-op.
// k==400 uses colsum (identical lane structure -> bit-equal).
__global__ void __launch_bounds__(512) k_recur()
{
    const int b = blockIdx.x;
    const int tid = threadIdx.x;
    const int lane = tid & 31;
    const int warp = tid >> 5;
    const bool act = tid < NEXC;
    const int j = act ? tid : 0;

    __shared__ unsigned smask[3][NW_EX];
    __shared__ unsigned short slist[3][NEXC + 8];
    __shared__ int scnt[3];

    if (tid < 3) scnt[tid] = 0;

    float v = 0.f;
    const float csum = g_colsum[j];
    const float* __restrict__ Dp = g_D + (size_t)b * T * NEXC + j;
    const float* __restrict__ Wj = g_wie + j;

    float dpf[4];
    #pragma unroll
    for (int u2 = 0; u2 < 4; u2++) dpf[u2] = Dp[(size_t)u2 * NEXC];
    __syncthreads();

    for (int tc = 0; tc < T; tc += 4) {
        #pragma unroll
        for (int u2 = 0; u2 < 4; u2++) {
            const int t = tc + u2;
            const float d = dpf[u2];
            {
                int tp = t + 4;
                dpf[u2] = (tp < T) ? Dp[(size_t)tp * NEXC] : 0.f;
            }

            // ---- inhibition from s[t-2] ----
            const int rs = (t + 1) % 3;
            float inh = 0.f;
            const int k = scnt[rs];
            if (k == NEXC) {
                inh = csum;
            } else if (k > 0) {
                const int len8 = (k + 7) & ~7;
                const unsigned short* L = slist[rs];
                float a0 = 0.f, a1 = 0.f, a2 = 0.f, a3 = 0.f;
                for (int m = 0; m < len8; m += 8) {
                    #pragma unroll
                    for (int q = 0; q < 8; q++) {
                        const int ii = L[m + q];
                        const float w = Wj[ii * NEXC];
                        const int ln = ii & 3;      // uniform across warp
                        if (ln == 0)      a0 = __fadd_rn(a0, w);
                        else if (ln == 1) a1 = __fadd_rn(a1, w);
                        else if (ln == 2) a2 = __fadd_rn(a2, w);
                        else              a3 = __fadd_rn(a3, w);
                    }
                }
                inh = __fadd_rn(__fadd_rn(a0, a1), __fadd_rn(a2, a3));
            }

            // ---- LIF step (exact JAX fp32 tree) ----
            const float I   = __fsub_rn(d, inh);
            const float t2v = __fmul_rn(0.01f, __fsub_rn(0.f, v));
            const float t3v = __fadd_rn(v, t2v);
            const float uu  = __fadd_rn(t3v, I);
            const bool  sp  = act && (uu >= 1.0f);
            v = (uu >= 1.0f) ? 0.f : uu;

            // ---- publish spikes ----
            const unsigned bw = __ballot_sync(0xFFFFFFFFu, sp);
            const int wslot = t % 3;
            if (warp < NW_EX && lane == 0) {
                smask[wslot][warp] = bw;
                g_sbits[((size_t)b * NW_EX + warp) * T + t] = bw;
            }
            __syncthreads();

            if (warp == 0) {
                unsigned wv = (lane < NW_EX) ? smask[wslot][lane] : 0u;
                int c = __popc(wv);
                #pragma unroll
                for (int o = 16; o; o >>= 1) c += __shfl_xor_sync(0xFFFFFFFFu, c, o);
                if (lane == 0) scnt[wslot] = c;
            }
            __syncthreads();

            const int kt = scnt[wslot];
            if (kt > 0 && kt < NEXC) {
                if (act) {
                    int off = 0;
                    #pragma unroll
                    for (int w2 = 0; w2 < NW_EX; w2++)
                        if (w2 < warp) off += __popc(smask[wslot][w2]);
                    const unsigned mym = smask[wslot][warp];
                    const unsigned lm = (1u << lane) - 1u;
                    const int rank = __popc(mym & lm);
                    if (sp) slist[wslot][off + rank] = (unsigned short)tid;
                }
                const int len8 = (kt + 7) & ~7;
                if (tid < len8 - kt) slist[wslot][kt + tid] = (unsigned short)NEXC;
            }
        }
    }
}

// ---------------- K4: expand spike bits -> fp32 outputs ---------------------
__global__ void k_expand(float* __restrict__ out, int both)
{
    size_t idx = (size_t)blockIdx.x * 256 + threadIdx.x;
    const size_t total = (size_t)B * NEXC * T;
    if (idx >= total) return;
    int t = (int)(idx % T);
    int bj = (int)(idx / T);
    int j = bj % NEXC;
    int b = bj / NEXC;
    const unsigned* wp = &g_sbits[((size_t)b * NW_EX + (j >> 5)) * T];
    unsigned w = wp[t];
    out[idx] = ((w >> (j & 31)) & 1u) ? 1.f : 0.f;
    if (both) {
        float inh = 0.f;
        if (t > 0) {
            unsigned w2 = wp[t - 1];
            inh = ((w2 >> (j & 31)) & 1u) ? 1.f : 0.f;
        }
        out[idx + total] = inh;
    }
}

// ---------------- launch ----------------------------------------------------
extern "C" void kernel_launch(void* const* d_in, const int* in_sizes, int n_in,
                              void* d_out, int out_size)
{
    const float* x    = (const float*)d_in[0];
    const float* w_in = (const float*)d_in[1];
    const float* w_ie = (const float*)d_in[2];
    float* out = (float*)d_out;

    cudaFuncSetAttribute(k_drive, cudaFuncAttributeMaxDynamicSharedMemorySize,
                         NIN * JT * (int)sizeof(float));

    k_prep<<<((NEXC + 1) * NEXC + 255) / 256, 256>>>(w_ie);
    k_colsum<<<(NEXC + 127) / 128, 128>>>();
    k_bitpack<<<B * NW_IN, 512>>>(x);
    k_drive<<<dim3(NJT, NCHUNK), 512, NIN * JT * (int)sizeof(float)>>>(w_in);
    k_recur<<<B, 512>>>();
    k_expand<<<((B * NEXC * T) + 255) / 256, 256>>>(
        out, (out_size >= 2 * B * NEXC * T) ? 1 : 0);
}

// round 17
// speedup vs baseline: 2.4238x; 2.4238x over previous
#include <cuda_runtime.h>
#include <cstdint>

#define B     128
#define NIN   784
#define NEXC  400
#define T     500
#define NW_IN 25
#define NW_EX 13
#define JT    64
#define NJT   7
#define NCHUNK 22
#define DTHREADS 1024
#define DWARPS   32
#define LSTR  104   // per-lane sub-list stride (max 100 active + pad)

typedef unsigned long long ull;

// -------- device scratch --------
__device__ float    g_D[(size_t)B * T * NEXC];
__device__ unsigned g_xbits[B * NW_IN * T];
__device__ unsigned g_sbits[B * NW_EX * T];
__device__ float    g_wie[(NEXC + 1) * NEXC];
__device__ float    g_colsum[NEXC];

// ---------------- K0a: masked/relu'd w_ie (+ zero pad row 400) --------------
__global__ void k_prep(const float* __restrict__ w)
{
    int idx = blockIdx.x * 256 + threadIdx.x;
    if (idx < (NEXC + 1) * NEXC) {
        float val = 0.f;
        if (idx < NEXC * NEXC) {
            int i = idx / NEXC, jj = idx - i * NEXC;
            float ww = w[idx];
            val = (i == jj) ? 0.f : fmaxf(ww, 0.f);
        }
        g_wie[idx] = val;
    }
}

// ---------------- K0b: column sums — 4-lane mod-4 + faddp tree (frozen) -----
__global__ void k_colsum()
{
    int j = blockIdx.x * 128 + threadIdx.x;
    if (j < NEXC) {
        float a0 = 0.f, a1 = 0.f, a2 = 0.f, a3 = 0.f;
        for (int i = 0; i < NEXC; i += 4) {
            a0 = __fadd_rn(a0, g_wie[(i + 0) * NEXC + j]);
            a1 = __fadd_rn(a1, g_wie[(i + 1) * NEXC + j]);
            a2 = __fadd_rn(a2, g_wie[(i + 2) * NEXC + j]);
            a3 = __fadd_rn(a3, g_wie[(i + 3) * NEXC + j]);
        }
        g_colsum[j] = __fadd_rn(__fadd_rn(a0, a1), __fadd_rn(a2, a3));
    }
}

// ---------------- K1: bit-pack input spikes ---------------------------------
__global__ void __launch_bounds__(512) k_bitpack(const float* __restrict__ x)
{
    int blk = blockIdx.x;
    int b = blk / NW_IN, iw = blk - b * NW_IN;
    int t = threadIdx.x;
    if (t >= T) return;
    int ibase = iw * 32;
    int nbits = min(32, NIN - ibase);
    const float* xp = x + ((size_t)b * NIN + ibase) * T + t;
    unsigned word = 0u;
    for (int r = 0; r < nbits; r++) {
        float v = xp[(size_t)r * T];
        word |= (v != 0.0f ? 1u : 0u) << r;
    }
    g_xbits[(b * NW_IN + iw) * T + t] = word;
}

// ---------------- K2: sparse drive, 4-lane mod-4 + faddp tree (frozen math) -
// 1024 threads (32 warps) for issue-side latency hiding; order unchanged.
__global__ void __launch_bounds__(DTHREADS) k_drive(const float* __restrict__ w_in)
{
    extern __shared__ float ws[];
    const int jt = blockIdx.x;
    const int chunk = blockIdx.y;
    const int j0 = jt * JT;

    for (int idx = threadIdx.x; idx < NIN * JT; idx += DTHREADS) {
        int i = idx >> 6, c = idx & 63;
        int j = j0 + c;
        ws[idx] = (j < NEXC) ? fmaxf(w_in[i * NEXC + j], 0.f) : 0.f;
    }
    __syncthreads();

    const int warp = threadIdx.x >> 5, lane = threadIdx.x & 31;
    const int per = (B * T + NCHUNK - 1) / NCHUNK;
    const int bt0 = chunk * per;
    const int btend = min(B * T, bt0 + per);

    for (int base = bt0 + warp * 2; base < btend; base += DWARPS * 2) {
        unsigned mw[2];
        ull pacc[2][4];
        #pragma unroll
        for (int c = 0; c < 2; c++) {
            int bt = base + c;
            unsigned m = 0u;
            if (bt < btend && lane < NW_IN) {
                int b = bt / T, t = bt - b * T;
                m = g_xbits[(b * NW_IN + lane) * T + t];
            }
            mw[c] = m;
            #pragma unroll
            for (int l2 = 0; l2 < 4; l2++) pacc[c][l2] = 0ull;
        }

        #pragma unroll
        for (int iw = 0; iw < NW_IN; iw++) {
            #pragma unroll
            for (int c = 0; c < 2; c++) {
                unsigned word = __shfl_sync(0xFFFFFFFFu, mw[c], iw);
                #pragma unroll
                for (int l2 = 0; l2 < 4; l2++) {
                    unsigned sw = word & (0x11111111u << l2);
                    while (sw) {
                        int r = __ffs(sw) - 1;
                        sw &= sw - 1;
                        ull wv = *reinterpret_cast<const ull*>(
                            &ws[(iw * 32 + r) * JT + 2 * lane]);
                        asm("add.rn.f32x2 %0, %0, %1;" : "+l"(pacc[c][l2]) : "l"(wv));
                    }
                }
            }
        }

        const int j = j0 + 2 * lane;
        if (j < NEXC) {
            #pragma unroll
            for (int c = 0; c < 2; c++) {
                int bt = base + c;
                if (bt < btend) {
                    ull t01, t23, res;
                    asm("add.rn.f32x2 %0, %1, %2;" : "=l"(t01) : "l"(pacc[c][0]), "l"(pacc[c][1]));
                    asm("add.rn.f32x2 %0, %1, %2;" : "=l"(t23) : "l"(pacc[c][2]), "l"(pacc[c][3]));
                    asm("add.rn.f32x2 %0, %1, %2;" : "=l"(res) : "l"(t01), "l"(t23));
                    *reinterpret_cast<ull*>(&g_D[(size_t)bt * NEXC + j]) = res;
                }
            }
        }
    }
}

// ---------------- K3: recurrence — per-lane sub-lists, batched gather -------
// Math identical to R15 (rel_err 0): lane l = ascending chain over active
// i ≡ l (mod 4); inh = (a0+a1)+(a2+a3). Sub-lists are branch-free and padded
// with idx 400 (zero row, exact no-op) to a common multiple of 8; gather does
// 32 batched L2 loads + 4 independent add-chains per iteration (ILP=4).
__global__ void __launch_bounds__(512) k_recur()
{
    const int b = blockIdx.x;
    const int tid = threadIdx.x;
    const int lane = tid & 31;
    const int warp = tid >> 5;
    const bool act = tid < NEXC;
    const int j = act ? tid : 0;

    __shared__ unsigned smask[3][NW_EX];
    __shared__ unsigned short slist[3][4 * LSTR];
    __shared__ int scnt4[3][4];

    if (tid < 12) scnt4[tid >> 2][tid & 3] = 0;

    float v = 0.f;
    const float csum = g_colsum[j];
    const float* __restrict__ Dp = g_D + (size_t)b * T * NEXC + j;
    const float* __restrict__ Wj = g_wie + j;

    float dpf[4];
    #pragma unroll
    for (int u2 = 0; u2 < 4; u2++) dpf[u2] = Dp[(size_t)u2 * NEXC];
    __syncthreads();

    for (int tc = 0; tc < T; tc += 4) {
        #pragma unroll
        for (int u2 = 0; u2 < 4; u2++) {
            const int t = tc + u2;
            const float d = dpf[u2];
            {
                int tp = t + 4;
                dpf[u2] = (tp < T) ? Dp[(size_t)tp * NEXC] : 0.f;
            }

            // ---- inhibition from s[t-2] (ring slot rs) ----
            const int rs = (t + 1) % 3;
            float inh = 0.f;
            const int c0 = scnt4[rs][0], c1 = scnt4[rs][1];
            const int c2 = scnt4[rs][2], c3 = scnt4[rs][3];
            const int k = c0 + c1 + c2 + c3;
            if (k == NEXC) {
                inh = csum;
            } else if (k > 0) {
                const int mx = max(max(c0, c1), max(c2, c3));
                const int L8 = (mx + 7) & ~7;
                const unsigned short* L = &slist[rs][0];
                float a0 = 0.f, a1 = 0.f, a2 = 0.f, a3 = 0.f;
                for (int m = 0; m < L8; m += 8) {
                    float w[4][8];
                    #pragma unroll
                    for (int l2 = 0; l2 < 4; l2++) {
                        #pragma unroll
                        for (int q = 0; q < 8; q++) {
                            const int ii = L[l2 * LSTR + m + q];
                            w[l2][q] = Wj[ii * NEXC];
                        }
                    }
                    #pragma unroll
                    for (int q = 0; q < 8; q++) {
                        a0 = __fadd_rn(a0, w[0][q]);
                        a1 = __fadd_rn(a1, w[1][q]);
                        a2 = __fadd_rn(a2, w[2][q]);
                        a3 = __fadd_rn(a3, w[3][q]);
                    }
                }
                inh = __fadd_rn(__fadd_rn(a0, a1), __fadd_rn(a2, a3));
            }

            // ---- LIF step (exact JAX fp32 tree, frozen) ----
            const float I   = __fsub_rn(d, inh);
            const float t2v = __fmul_rn(0.01f, __fsub_rn(0.f, v));
            const float t3v = __fadd_rn(v, t2v);
            const float uu  = __fadd_rn(t3v, I);
            const bool  sp  = act && (uu >= 1.0f);
            v = (uu >= 1.0f) ? 0.f : uu;

            // ---- publish spikes ----
            const unsigned bw = __ballot_sync(0xFFFFFFFFu, sp);
            const int wslot = t % 3;
            if (warp < NW_EX && lane == 0) {
                smask[wslot][warp] = bw;
                g_sbits[((size_t)b * NW_EX + warp) * T + t] = bw;
            }
            __syncthreads();   // S1: masks visible

            // per-lane counts (warp 0, lanes 0-3)
            if (warp == 0 && lane < 4) {
                const unsigned LM = 0x11111111u << lane;
                int c = 0;
                #pragma unroll
                for (int w2 = 0; w2 < NW_EX; w2++)
                    c += __popc(smask[wslot][w2] & LM);
                scnt4[wslot][lane] = c;
            }
            __syncthreads();   // S2: counts visible

            const int k0 = scnt4[wslot][0], k1 = scnt4[wslot][1];
            const int k2 = scnt4[wslot][2], k3 = scnt4[wslot][3];
            const int kt = k0 + k1 + k2 + k3;
            if (kt > 0 && kt < NEXC) {
                const int mx = max(max(k0, k1), max(k2, k3));
                const int L8 = (mx + 7) & ~7;
                // write own index into per-lane sub-list (ascending within lane)
                if (sp) {
                    const int l = tid & 3;
                    const unsigned LM = 0x11111111u << l;
                    int rank = 0;
                    #pragma unroll
                    for (int w2 = 0; w2 < NW_EX; w2++)
                        if (w2 < warp) rank += __popc(smask[wslot][w2] & LM);
                    const unsigned lm = (1u << lane) - 1u;
                    rank += __popc(smask[wslot][warp] & LM & lm);
                    slist[wslot][l * LSTR + rank] = (unsigned short)tid;
                }
                // pad each lane to L8 with idx 400 (zero row)
                const int kk[4] = {k0, k1, k2, k3};
                #pragma unroll
                for (int l = 0; l < 4; l++)
                    if (tid < L8 - kk[l])
                        slist[wslot][l * LSTR + kk[l] + tid] = (unsigned short)NEXC;
            }
            // slot written here is next read at t+2, after t+1's syncs -> safe
        }
    }
}

// ---------------- K4: expand spike bits -> fp32 outputs ---------------------
__global__ void k_expand(float* __restrict__ out, int both)
{
    size_t idx = (size_t)blockIdx.x * 256 + threadIdx.x;
    const size_t total = (size_t)B * NEXC * T;
    if (idx >= total) return;
    int t = (int)(idx % T);
    int bj = (int)(idx / T);
    int j = bj % NEXC;
    int b = bj / NEXC;
    const unsigned* wp = &g_sbits[((size_t)b * NW_EX + (j >> 5)) * T];
    unsigned w = wp[t];
    out[idx] = ((w >> (j & 31)) & 1u) ? 1.f : 0.f;
    if (both) {
        float inh = 0.f;
        if (t > 0) {
            unsigned w2 = wp[t - 1];
            inh = ((w2 >> (j & 31)) & 1u) ? 1.f : 0.f;
        }
        out[idx + total] = inh;
    }
}

// ---------------- launch ----------------------------------------------------
extern "C" void kernel_launch(void* const* d_in, const int* in_sizes, int n_in,
                              void* d_out, int out_size)
{
    const float* x    = (const float*)d_in[0];
    const float* w_in = (const float*)d_in[1];
    const float* w_ie = (const float*)d_in[2];
    float* out = (float*)d_out;

    cudaFuncSetAttribute(k_drive, cudaFuncAttributeMaxDynamicSharedMemorySize,
                         NIN * JT * (int)sizeof(float));

    k_prep<<<((NEXC + 1) * NEXC + 255) / 256, 256>>>(w_ie);
    k_colsum<<<(NEXC + 127) / 128, 128>>>();
    k_bitpack<<<B * NW_IN, 512>>>(x);
    k_drive<<<dim3(NJT, NCHUNK), DTHREADS, NIN * JT * (int)sizeof(float)>>>(w_in);
    k_recur<<<B, 512>>>();
    k_expand<<<((B * NEXC * T) + 255) / 256, 256>>>(
        out, (out_size >= 2 * B * NEXC * T) ? 1 : 0);
}